// round 3
// baseline (speedup 1.0000x reference)
#include <cuda_runtime.h>

// DenseQConv1D analytic collapse (exact):
//   out[b,c,l] = cos(theta[c,0]) * (S_even - S_odd) / max(S_total, 1e-24)
//   with S_* = windowed 8-tap sums of a[b,l] = sum_cin x[b,cin,l]^2.
// Derivation: out = s^T (E R) S (E R)^T s ; R S R^T = H(theta0) (x) I^8 ;
// E = CNOT-ring permutation (linear over GF(2)); conjugated M_c is
// diag(+/-cos(theta[c,0])) on the 128-dim patch support, sign = (-1)^(j&1).
//
// R3: back to 64 CTAs x 128 thr (R2 showed fewer/fatter CTAs win).
//     Halo loads issued in parallel with main loads (single DRAM trip on the
//     critical path instead of two), fast divide, cosf hoisted over latency.

#define BB 8
#define C_IN 16
#define C_OUT 16
#define LL 1024
#define KK 8
#define L_OUT (LL - KK + 1)   // 1017
#define TL 128                // l-positions per block
#define NQ 9

__global__ __launch_bounds__(TL) void DenseQConv1D_84542136255139_kernel(
    const float* __restrict__ x,      // [B, C_IN, L]
    const float* __restrict__ theta,  // [C_OUT, NQ]
    float* __restrict__ out)          // [B, C_OUT, L_OUT]
{
    __shared__ float a[TL + KK];      // channel-reduced squares + 7 halo
    __shared__ float cosv[C_OUT];

    const int b   = blockIdx.y;
    const int l0  = blockIdx.x * TL;
    const int tid = threadIdx.x;

    // theta load + cos overlap the x-load latency below.
    if (tid < C_OUT) cosv[tid] = cosf(theta[tid * NQ]);

    // Phase 1: a[i] = sum_c x[b,c,l0+i]^2.
    // Main value i=tid for all threads; halo i=tid+TL for tid<7, accumulated
    // in the SAME instruction stream so all loads are in flight together.
    {
        const float* xb = x + (size_t)b * (C_IN * LL) + l0 + tid;
        const bool halo  = (tid < KK - 1);
        const bool main_ok = (l0 + tid < LL);          // last tile guard
        float s  = 0.0f;
        float s2 = 0.0f;
        #pragma unroll
        for (int c = 0; c < C_IN; ++c) {
            float v  = main_ok ? xb[c * LL]      : 0.0f;
            float v2 = halo    ? xb[c * LL + TL] : 0.0f;
            s  = fmaf(v,  v,  s);
            s2 = fmaf(v2, v2, s2);
        }
        a[tid] = s;
        if (halo) a[tid + TL] = s2;
    }
    __syncthreads();

    // Phase 2: alternating / total window sums, 16 channel stores.
    const int l = l0 + tid;
    if (l < L_OUT) {
        float se = a[tid]     + a[tid + 2] + a[tid + 4] + a[tid + 6];
        float so = a[tid + 1] + a[tid + 3] + a[tid + 5] + a[tid + 7];
        float tot = se + so;
        float r = __fdividef(se - so, fmaxf(tot, 1e-24f));
        float* ob = out + (size_t)b * (C_OUT * L_OUT) + l;
        #pragma unroll
        for (int c = 0; c < C_OUT; ++c) {
            ob[c * L_OUT] = cosv[c] * r;
        }
    }
}

extern "C" void kernel_launch(void* const* d_in, const int* in_sizes, int n_in,
                              void* d_out, int out_size)
{
    // Resolve inputs by element count (robust to metadata ordering):
    //   x: 131072, theta: 144, entangle: 262144 (unused)
    const float* x = nullptr;
    const float* theta = nullptr;
    for (int i = 0; i < n_in; ++i) {
        if (in_sizes[i] == BB * C_IN * LL)      x     = (const float*)d_in[i];
        else if (in_sizes[i] == C_OUT * NQ)     theta = (const float*)d_in[i];
    }

    dim3 grid((L_OUT + TL - 1) / TL, BB);   // 8 x 8 = 64 CTAs
    DenseQConv1D_84542136255139_kernel<<<grid, TL>>>(x, theta, (float*)d_out);
}